// round 4
// baseline (speedup 1.0000x reference)
// R4: single-wave design — fixup fused into main pass via per-head last-block-done;
//     smem-staged coalesced stores for scales/zeros/pos side channels.
#include <cuda_runtime.h>
#include <cstdint>

#define NH 32
#define NL 8192
#define ND 128
#define ROWS_PER_BLK 8
#define NBLK ((NH * NL) / ROWS_PER_BLK)      // 32768 blocks
#define BLK_PER_HEAD (NL / ROWS_PER_BLK)     // 1024

// ---- output layout (float32 elements, reference return order) ----
#define KV_HALF   ((size_t)NH * NL * ND)
#define OFF_KV    ((size_t)0)
#define OFF_NI    (OFF_KV + 2 * KV_HALF)
#define OFF_POS   (OFF_NI + NH)
#define OFF_KQ    (OFF_POS + (size_t)NH * NL)
#define OFF_KS    (OFF_KQ + KV_HALF)
#define OFF_KZ    (OFF_KS + (size_t)NH * NL)
#define OFF_VQ    (OFF_KZ + (size_t)NH * NL)
#define OFF_VS    (OFF_VQ + KV_HALF)
#define OFF_VZ    (OFF_VS + (size_t)NH * NL)

// per-block partial argmin keys (every slot written every launch -> no init)
__device__ unsigned long long g_partial[NBLK];
// per-head completion counters; last block resets its own -> graph-replay safe
__device__ unsigned int g_done[NH];

__device__ __forceinline__ unsigned int orderable(float f) {
    unsigned int u = __float_as_uint(f);
    return (u & 0x80000000u) ? ~u : (u | 0x80000000u);
}

__device__ __forceinline__ float4 requant4(float a, float b, float c, float d,
                                           float mn, float sn) {
    float q0 = fminf(fmaxf(rintf(__fdiv_rn(__fsub_rn(a, mn), sn)), 0.0f), 15.0f);
    float q1 = fminf(fmaxf(rintf(__fdiv_rn(__fsub_rn(b, mn), sn)), 0.0f), 15.0f);
    float q2 = fminf(fmaxf(rintf(__fdiv_rn(__fsub_rn(c, mn), sn)), 0.0f), 15.0f);
    float q3 = fminf(fmaxf(rintf(__fdiv_rn(__fsub_rn(d, mn), sn)), 0.0f), 15.0f);
    return make_float4(q0, q1, q2, q3);
}

// One warp per token row, 8 warps per block. Last block per head does fixup.
__global__ __launch_bounds__(256) void main_pass_kernel(
    const int*   __restrict__ kq,
    const int*   __restrict__ vq,
    const float* __restrict__ ks,
    const float* __restrict__ kz,
    const float* __restrict__ vs,
    const float* __restrict__ vz,
    const int*   __restrict__ pos,
    const int*   __restrict__ input_pos,
    const float* __restrict__ k_val,
    const float* __restrict__ v_val,
    const float* __restrict__ w,
    float*       __restrict__ out)
{
    const int warp = threadIdx.x >> 5;
    const int lane = threadIdx.x & 31;
    const int tid  = threadIdx.x;
    const int r = blockIdx.x * ROWS_PER_BLK + warp;
    const int h = r >> 13;
    const int l = r & (NL - 1);

    const size_t rowoff = (size_t)r * ND;
    const int d0 = lane * 4;

    const int4 kqi = __ldcs((const int4*)(kq + rowoff + d0));
    const int4 vqi = __ldcs((const int4*)(vq + rowoff + d0));
    const float sk = ks[r], zk = kz[r];
    const float sv = vs[r], zv = vz[r];
    const float4 wv = *(const float4*)(w + (size_t)h * ND + d0);

    // ---- dequantize K (match jnp: mul then add, separately rounded) ----
    float k0 = __fadd_rn(__fmul_rn((float)kqi.x, sk), zk);
    float k1 = __fadd_rn(__fmul_rn((float)kqi.y, sk), zk);
    float k2 = __fadd_rn(__fmul_rn((float)kqi.z, sk), zk);
    float k3 = __fadd_rn(__fmul_rn((float)kqi.w, sk), zk);
    __stcs((float4*)(out + OFF_KV + rowoff + d0), make_float4(k0, k1, k2, k3));

    // ---- dequantize V ----
    float v0 = __fadd_rn(__fmul_rn((float)vqi.x, sv), zv);
    float v1 = __fadd_rn(__fmul_rn((float)vqi.y, sv), zv);
    float v2 = __fadd_rn(__fmul_rn((float)vqi.z, sv), zv);
    float v3 = __fadd_rn(__fmul_rn((float)vqi.w, sv), zv);
    __stcs((float4*)(out + OFF_KV + KV_HALF + rowoff + d0), make_float4(v0, v1, v2, v3));

    // ---- score = dot(k_row, w[h]) ----
    float dp = k0 * wv.x + k1 * wv.y + k2 * wv.z + k3 * wv.w;
    #pragma unroll
    for (int o = 16; o; o >>= 1) dp += __shfl_xor_sync(0xFFFFFFFFu, dp, o);

    // ---- requantize K via integer min/max (monotone affine dequant) ----
    int kmn = min(min(kqi.x, kqi.y), min(kqi.z, kqi.w));
    int kmx = max(max(kqi.x, kqi.y), max(kqi.z, kqi.w));
    kmn = __reduce_min_sync(0xFFFFFFFFu, kmn);
    kmx = __reduce_max_sync(0xFFFFFFFFu, kmx);
    float kmnf = __fadd_rn(__fmul_rn((float)kmn, sk), zk);
    float kmxf = __fadd_rn(__fmul_rn((float)kmx, sk), zk);
    float ksn  = fmaxf(__fdiv_rn(__fsub_rn(kmxf, kmnf), 15.0f), 1e-6f);
    __stcs((float4*)(out + OFF_KQ + rowoff + d0), requant4(k0, k1, k2, k3, kmnf, ksn));

    // ---- requantize V ----
    int vmn = min(min(vqi.x, vqi.y), min(vqi.z, vqi.w));
    int vmx = max(max(vqi.x, vqi.y), max(vqi.z, vqi.w));
    vmn = __reduce_min_sync(0xFFFFFFFFu, vmn);
    vmx = __reduce_max_sync(0xFFFFFFFFu, vmx);
    float vmnf = __fadd_rn(__fmul_rn((float)vmn, sv), zv);
    float vmxf = __fadd_rn(__fmul_rn((float)vmx, sv), zv);
    float vsn  = fmaxf(__fdiv_rn(__fsub_rn(vmxf, vmnf), 15.0f), 1e-6f);
    __stcs((float4*)(out + OFF_VQ + rowoff + d0), requant4(v0, v1, v2, v3, vmnf, vsn));

    // ---- smem staging: per-row scalars + argmin keys ----
    __shared__ float s_ks[ROWS_PER_BLK], s_kz[ROWS_PER_BLK];
    __shared__ float s_vs[ROWS_PER_BLK], s_vz[ROWS_PER_BLK];
    __shared__ int   s_p[ROWS_PER_BLK];
    __shared__ unsigned long long skey[ROWS_PER_BLK];
    __shared__ unsigned int s_ticket;

    if (lane == 0) {
        int p = pos[r];
        s_ks[warp] = ksn;  s_kz[warp] = kmnf;
        s_vs[warp] = vsn;  s_vz[warp] = vmnf;
        s_p[warp]  = p;
        float sc = dp;
        if (l < 4)   sc = __int_as_float(0x7F800000);   // +inf: protect global tokens
        if (p == -1) sc = __int_as_float(0xFF800000);   // -inf: empty slot first
        skey[warp] = ((unsigned long long)orderable(sc) << 32) | (unsigned)l;
    }
    __syncthreads();

    // coalesced 32B stores for the five scalar streams
    const int rb = blockIdx.x * ROWS_PER_BLK;
    if (warp == 0 && lane < ROWS_PER_BLK) {
        out[OFF_KS  + rb + lane] = s_ks[lane];
        out[OFF_KZ  + rb + lane] = s_kz[lane];
        out[OFF_VS  + rb + lane] = s_vs[lane];
        out[OFF_VZ  + rb + lane] = s_vz[lane];
        out[OFF_POS + rb + lane] = (float)s_p[lane];
    }
    if (warp == 1) {
        unsigned long long kk = (lane < ROWS_PER_BLK) ? skey[lane] : 0xFFFFFFFFFFFFFFFFULL;
        #pragma unroll
        for (int o = 4; o; o >>= 1) {
            unsigned long long other = __shfl_xor_sync(0xFFFFFFFFu, kk, o);
            kk = (other < kk) ? other : kk;
        }
        if (lane == 0) g_partial[blockIdx.x] = kk;
    }

    // ---- publish + per-head completion count ----
    __threadfence();                       // each thread publishes its stores
    __syncthreads();                       // order fences before the atomic
    if (tid == 0) s_ticket = atomicAdd(&g_done[h], 1u);
    __syncthreads();
    if (s_ticket != BLK_PER_HEAD - 1) return;

    // ======== LAST BLOCK OF THIS HEAD: fixup ========
    if (tid == 0) g_done[h] = 0;           // reset for next graph replay
    __threadfence();                       // acquire side

    // reduce this head's 1024 partial keys
    unsigned long long kk = 0xFFFFFFFFFFFFFFFFULL;
    #pragma unroll
    for (int i = tid; i < BLK_PER_HEAD; i += 256) {
        unsigned long long v = __ldcg(&g_partial[h * BLK_PER_HEAD + i]);
        kk = (v < kk) ? v : kk;
    }
    #pragma unroll
    for (int o = 16; o; o >>= 1) {
        unsigned long long other = __shfl_xor_sync(0xFFFFFFFFu, kk, o);
        kk = (other < kk) ? other : kk;
    }
    __shared__ unsigned long long swk[8];
    __shared__ int sidx;
    if (lane == 0) swk[warp] = kk;
    __syncthreads();
    if (tid == 0) {
        unsigned long long m = swk[0];
        #pragma unroll
        for (int i = 1; i < 8; i++) m = (swk[i] < m) ? swk[i] : m;
        sidx = (int)(unsigned int)(m & 0xFFFFFFFFu);
    }
    __syncthreads();

    if (warp != 0) return;
    const int idx = sidx;
    const int re = h * NL + idx;
    const size_t eoff = (size_t)re * ND;

    if (lane == 0) {
        out[OFF_NI + h]   = (pos[re] == -1) ? 1.0f : 0.0f;
        out[OFF_POS + re] = (float)input_pos[0];
    }

    // K side
    {
        float4 x = *(const float4*)(k_val + (size_t)h * ND + d0);
        *(float4*)(out + OFF_KV + eoff + d0) = x;
        float mn = fminf(fminf(x.x, x.y), fminf(x.z, x.w));
        float mx = fmaxf(fmaxf(x.x, x.y), fmaxf(x.z, x.w));
        #pragma unroll
        for (int o = 16; o; o >>= 1) {
            mn = fminf(mn, __shfl_xor_sync(0xFFFFFFFFu, mn, o));
            mx = fmaxf(mx, __shfl_xor_sync(0xFFFFFFFFu, mx, o));
        }
        float sn = fmaxf(__fdiv_rn(__fsub_rn(mx, mn), 15.0f), 1e-6f);
        *(float4*)(out + OFF_KQ + eoff + d0) = requant4(x.x, x.y, x.z, x.w, mn, sn);
        if (lane == 0) { out[OFF_KS + re] = sn; out[OFF_KZ + re] = mn; }
    }
    // V side
    {
        float4 x = *(const float4*)(v_val + (size_t)h * ND + d0);
        *(float4*)(out + OFF_KV + KV_HALF + eoff + d0) = x;
        float mn = fminf(fminf(x.x, x.y), fminf(x.z, x.w));
        float mx = fmaxf(fmaxf(x.x, x.y), fmaxf(x.z, x.w));
        #pragma unroll
        for (int o = 16; o; o >>= 1) {
            mn = fminf(mn, __shfl_xor_sync(0xFFFFFFFFu, mn, o));
            mx = fmaxf(mx, __shfl_xor_sync(0xFFFFFFFFu, mx, o));
        }
        float sn = fmaxf(__fdiv_rn(__fsub_rn(mx, mn), 15.0f), 1e-6f);
        *(float4*)(out + OFF_VQ + eoff + d0) = requant4(x.x, x.y, x.z, x.w, mn, sn);
        if (lane == 0) { out[OFF_VS + re] = sn; out[OFF_VZ + re] = mn; }
    }
}

extern "C" void kernel_launch(void* const* d_in, const int* in_sizes, int n_in,
                              void* d_out, int out_size)
{
    const int*   kq  = (const int*)  d_in[0];
    const int*   vq  = (const int*)  d_in[1];
    const float* ks  = (const float*)d_in[2];
    const float* kz  = (const float*)d_in[3];
    const float* vs  = (const float*)d_in[4];
    const float* vz  = (const float*)d_in[5];
    const int*   pos = (const int*)  d_in[6];
    const int*   ip  = (const int*)  d_in[7];
    const float* kv_ = (const float*)d_in[8];
    const float* vv_ = (const float*)d_in[9];
    const float* w   = (const float*)d_in[10];
    float* out = (float*)d_out;

    main_pass_kernel<<<NBLK, 256>>>(kq, vq, ks, kz, vs, vz, pos, ip, kv_, vv_, w, out);
}

// round 5
// speedup vs baseline: 1.4087x; 1.4087x over previous
// R5: revert fence-fusion (two launches, like R3) + 16-entry table-shuffle
//     requant/dequant (kills the per-element __fdiv_rn ALU wall) + coalesced
//     scalar side-channel stores (from R4).
#include <cuda_runtime.h>
#include <cstdint>

#define NH 32
#define NL 8192
#define ND 128
#define ROWS_PER_BLK 8
#define NBLK ((NH * NL) / ROWS_PER_BLK)      // 32768
#define BLK_PER_HEAD (NL / ROWS_PER_BLK)     // 1024

#define KV_HALF   ((size_t)NH * NL * ND)
#define OFF_KV    ((size_t)0)
#define OFF_NI    (OFF_KV + 2 * KV_HALF)
#define OFF_POS   (OFF_NI + NH)
#define OFF_KQ    (OFF_POS + (size_t)NH * NL)
#define OFF_KS    (OFF_KQ + KV_HALF)
#define OFF_KZ    (OFF_KS + (size_t)NH * NL)
#define OFF_VQ    (OFF_KZ + (size_t)NH * NL)
#define OFF_VS    (OFF_VQ + KV_HALF)
#define OFF_VZ    (OFF_VS + (size_t)NH * NL)

__device__ unsigned long long g_partial[NBLK];   // written every launch -> no init

__device__ __forceinline__ unsigned int orderable(float f) {
    unsigned int u = __float_as_uint(f);
    return (u & 0x80000000u) ? ~u : (u | 0x80000000u);
}

// One warp per token row, 8 warps per block.
__global__ __launch_bounds__(256) void main_pass_kernel(
    const int*   __restrict__ kq,
    const int*   __restrict__ vq,
    const float* __restrict__ ks,
    const float* __restrict__ kz,
    const float* __restrict__ vs,
    const float* __restrict__ vz,
    const int*   __restrict__ pos,
    const float* __restrict__ w,
    float*       __restrict__ out)
{
    const int warp = threadIdx.x >> 5;
    const int lane = threadIdx.x & 31;
    const int r = blockIdx.x * ROWS_PER_BLK + warp;
    const int h = r >> 13;
    const int l = r & (NL - 1);

    const size_t rowoff = (size_t)r * ND;
    const int d0 = lane * 4;

    const int4 kqi = __ldcs((const int4*)(kq + rowoff + d0));
    const int4 vqi = __ldcs((const int4*)(vq + rowoff + d0));
    const float sk = ks[r], zk = kz[r];
    const float sv = vs[r], zv = vz[r];
    const float4 wv = *(const float4*)(w + (size_t)h * ND + d0);

    // ---- per-row 16-entry dequant table (K in lanes 0-15, V in lanes 16-31) ----
    // dq_t = fl(fl(t*s) + z): identical op sequence to per-element dequant.
    const int   t  = lane & 15;
    const float s_ = (lane < 16) ? sk : sv;
    const float z_ = (lane < 16) ? zk : zv;
    const float dq_t = __fadd_rn(__fmul_rn((float)t, s_), z_);

    // ---- dequantize via table shuffle ----
    float k0 = __shfl_sync(0xFFFFFFFFu, dq_t, kqi.x);
    float k1 = __shfl_sync(0xFFFFFFFFu, dq_t, kqi.y);
    float k2 = __shfl_sync(0xFFFFFFFFu, dq_t, kqi.z);
    float k3 = __shfl_sync(0xFFFFFFFFu, dq_t, kqi.w);
    __stcs((float4*)(out + OFF_KV + rowoff + d0), make_float4(k0, k1, k2, k3));

    float v0 = __shfl_sync(0xFFFFFFFFu, dq_t, vqi.x | 16);
    float v1 = __shfl_sync(0xFFFFFFFFu, dq_t, vqi.y | 16);
    float v2 = __shfl_sync(0xFFFFFFFFu, dq_t, vqi.z | 16);
    float v3 = __shfl_sync(0xFFFFFFFFu, dq_t, vqi.w | 16);
    __stcs((float4*)(out + OFF_KV + KV_HALF + rowoff + d0), make_float4(v0, v1, v2, v3));

    // ---- score = dot(k_row, w[h]) ----
    float dp = k0 * wv.x + k1 * wv.y + k2 * wv.z + k3 * wv.w;
    #pragma unroll
    for (int o = 16; o; o >>= 1) dp += __shfl_xor_sync(0xFFFFFFFFu, dp, o);

    // ---- row integer min/max (monotone affine dequant -> endpoints) ----
    int kmn = min(min(kqi.x, kqi.y), min(kqi.z, kqi.w));
    int kmx = max(max(kqi.x, kqi.y), max(kqi.z, kqi.w));
    kmn = __reduce_min_sync(0xFFFFFFFFu, kmn);
    kmx = __reduce_max_sync(0xFFFFFFFFu, kmx);
    int vmn = min(min(vqi.x, vqi.y), min(vqi.z, vqi.w));
    int vmx = max(max(vqi.x, vqi.y), max(vqi.z, vqi.w));
    vmn = __reduce_min_sync(0xFFFFFFFFu, vmn);
    vmx = __reduce_max_sync(0xFFFFFFFFu, vmx);

    const float kmnf = __fadd_rn(__fmul_rn((float)kmn, sk), zk);
    const float kmxf = __fadd_rn(__fmul_rn((float)kmx, sk), zk);
    const float ksn  = fmaxf(__fdiv_rn(__fsub_rn(kmxf, kmnf), 15.0f), 1e-6f);
    const float vmnf = __fadd_rn(__fmul_rn((float)vmn, sv), zv);
    const float vmxf = __fadd_rn(__fmul_rn((float)vmx, sv), zv);
    const float vsn  = fmaxf(__fdiv_rn(__fsub_rn(vmxf, vmnf), 15.0f), 1e-6f);

    // ---- per-row 16-entry REQUANT table: one div per lane (vs 8/thread) ----
    const float mn_ = (lane < 16) ? kmnf : vmnf;
    const float sn_ = (lane < 16) ? ksn  : vsn;
    const float rq_t = fminf(fmaxf(rintf(__fdiv_rn(__fsub_rn(dq_t, mn_), sn_)), 0.0f), 15.0f);

    {
        float q0 = __shfl_sync(0xFFFFFFFFu, rq_t, kqi.x);
        float q1 = __shfl_sync(0xFFFFFFFFu, rq_t, kqi.y);
        float q2 = __shfl_sync(0xFFFFFFFFu, rq_t, kqi.z);
        float q3 = __shfl_sync(0xFFFFFFFFu, rq_t, kqi.w);
        __stcs((float4*)(out + OFF_KQ + rowoff + d0), make_float4(q0, q1, q2, q3));
    }
    {
        float q0 = __shfl_sync(0xFFFFFFFFu, rq_t, vqi.x | 16);
        float q1 = __shfl_sync(0xFFFFFFFFu, rq_t, vqi.y | 16);
        float q2 = __shfl_sync(0xFFFFFFFFu, rq_t, vqi.z | 16);
        float q3 = __shfl_sync(0xFFFFFFFFu, rq_t, vqi.w | 16);
        __stcs((float4*)(out + OFF_VQ + rowoff + d0), make_float4(q0, q1, q2, q3));
    }

    // ---- smem staging for coalesced scalar stores + argmin key ----
    __shared__ float s_ks[ROWS_PER_BLK], s_kz[ROWS_PER_BLK];
    __shared__ float s_vs[ROWS_PER_BLK], s_vz[ROWS_PER_BLK];
    __shared__ int   s_p[ROWS_PER_BLK];
    __shared__ unsigned long long skey[ROWS_PER_BLK];

    if (lane == 0) {
        int p = pos[r];
        s_ks[warp] = ksn;  s_kz[warp] = kmnf;
        s_vs[warp] = vsn;  s_vz[warp] = vmnf;
        s_p[warp]  = p;
        float sc = dp;
        if (l < 4)   sc = __int_as_float(0x7F800000);   // +inf: protect global tokens
        if (p == -1) sc = __int_as_float(0xFF800000);   // -inf: empty slot first
        skey[warp] = ((unsigned long long)orderable(sc) << 32) | (unsigned)l;
    }
    __syncthreads();

    const int rb = blockIdx.x * ROWS_PER_BLK;
    if (warp == 0 && lane < ROWS_PER_BLK) {
        out[OFF_KS  + rb + lane] = s_ks[lane];
        out[OFF_KZ  + rb + lane] = s_kz[lane];
        out[OFF_VS  + rb + lane] = s_vs[lane];
        out[OFF_VZ  + rb + lane] = s_vz[lane];
        out[OFF_POS + rb + lane] = (float)s_p[lane];
    }
    if (warp == 1) {
        unsigned long long kk = (lane < ROWS_PER_BLK) ? skey[lane] : 0xFFFFFFFFFFFFFFFFULL;
        #pragma unroll
        for (int o = 4; o; o >>= 1) {
            unsigned long long other = __shfl_xor_sync(0xFFFFFFFFu, kk, o);
            kk = (other < kk) ? other : kk;
        }
        if (lane == 0) g_partial[blockIdx.x] = kk;
    }
}

// One block (128 threads) per head: reduce 1024 partial keys, then warp 0 fixes
// up the evicted row (insert k_val/v_val, requant, pos_new, num_insertions).
__global__ __launch_bounds__(128) void fixup_kernel(
    const int*   __restrict__ pos,
    const int*   __restrict__ input_pos,
    const float* __restrict__ k_val,
    const float* __restrict__ v_val,
    float*       __restrict__ out)
{
    const int h = blockIdx.x;
    const int t = threadIdx.x;
    const int lane = t & 31;
    const int wrp = t >> 5;

    __shared__ unsigned long long swk[4];
    __shared__ int sidx;

    unsigned long long kk = 0xFFFFFFFFFFFFFFFFULL;
    #pragma unroll
    for (int i = t; i < BLK_PER_HEAD; i += 128) {
        unsigned long long v = g_partial[h * BLK_PER_HEAD + i];
        kk = (v < kk) ? v : kk;
    }
    #pragma unroll
    for (int o = 16; o; o >>= 1) {
        unsigned long long other = __shfl_xor_sync(0xFFFFFFFFu, kk, o);
        kk = (other < kk) ? other : kk;
    }
    if (lane == 0) swk[wrp] = kk;
    __syncthreads();
    if (t == 0) {
        unsigned long long m = swk[0];
        #pragma unroll
        for (int i = 1; i < 4; i++) m = (swk[i] < m) ? swk[i] : m;
        sidx = (int)(unsigned int)(m & 0xFFFFFFFFu);
    }
    __syncthreads();

    if (wrp != 0) return;
    const int idx = sidx;
    const int r = h * NL + idx;
    const size_t rowoff = (size_t)r * ND;
    const int d0 = lane * 4;

    if (lane == 0) {
        out[OFF_NI + h]  = (pos[r] == -1) ? 1.0f : 0.0f;
        out[OFF_POS + r] = (float)input_pos[0];
    }

    #pragma unroll
    for (int side = 0; side < 2; side++) {
        const float* val = side ? v_val : k_val;
        const size_t kvoff = OFF_KV + side * KV_HALF + rowoff;
        const size_t qoff  = (side ? OFF_VQ : OFF_KQ) + rowoff;
        float4 x = *(const float4*)(val + (size_t)h * ND + d0);
        *(float4*)(out + kvoff + d0) = x;
        float mn = fminf(fminf(x.x, x.y), fminf(x.z, x.w));
        float mx = fmaxf(fmaxf(x.x, x.y), fmaxf(x.z, x.w));
        #pragma unroll
        for (int o = 16; o; o >>= 1) {
            mn = fminf(mn, __shfl_xor_sync(0xFFFFFFFFu, mn, o));
            mx = fmaxf(mx, __shfl_xor_sync(0xFFFFFFFFu, mx, o));
        }
        float sn = fmaxf(__fdiv_rn(__fsub_rn(mx, mn), 15.0f), 1e-6f);
        float q0 = fminf(fmaxf(rintf(__fdiv_rn(__fsub_rn(x.x, mn), sn)), 0.0f), 15.0f);
        float q1 = fminf(fmaxf(rintf(__fdiv_rn(__fsub_rn(x.y, mn), sn)), 0.0f), 15.0f);
        float q2 = fminf(fmaxf(rintf(__fdiv_rn(__fsub_rn(x.z, mn), sn)), 0.0f), 15.0f);
        float q3 = fminf(fmaxf(rintf(__fdiv_rn(__fsub_rn(x.w, mn), sn)), 0.0f), 15.0f);
        *(float4*)(out + qoff + d0) = make_float4(q0, q1, q2, q3);
        if (lane == 0) {
            out[(side ? OFF_VS : OFF_KS) + r] = sn;
            out[(side ? OFF_VZ : OFF_KZ) + r] = mn;
        }
    }
}

extern "C" void kernel_launch(void* const* d_in, const int* in_sizes, int n_in,
                              void* d_out, int out_size)
{
    const int*   kq  = (const int*)  d_in[0];
    const int*   vq  = (const int*)  d_in[1];
    const float* ks  = (const float*)d_in[2];
    const float* kz  = (const float*)d_in[3];
    const float* vs  = (const float*)d_in[4];
    const float* vz  = (const float*)d_in[5];
    const int*   pos = (const int*)  d_in[6];
    const int*   ip  = (const int*)  d_in[7];
    const float* kv_ = (const float*)d_in[8];
    const float* vv_ = (const float*)d_in[9];
    const float* w   = (const float*)d_in[10];
    float* out = (float*)d_out;

    main_pass_kernel<<<NBLK, 256>>>(kq, vq, ks, kz, vs, vz, pos, w, out);
    fixup_kernel<<<NH, 128>>>(pos, ip, kv_, vv_, out);
}